// round 2
// baseline (speedup 1.0000x reference)
#include <cuda_runtime.h>
#include <math.h>

#define NN 100000
#define NE 600000
#define DD 128

// ---------------- scratch (device globals: allocation-free) ----------------
__device__ float g_xl[NN * DD];   // x_low  @ W_l
__device__ float g_xr[NN * DD];   // x_high @ W_r
__device__ float g_e[NE];         // per-edge attention logits
__device__ int   g_deg[NN];
__device__ int   g_off[NN + 1];
__device__ int   g_cur[NN];
__device__ int   g_eid[NE];       // CSR (by dst) edge ids

// ---------------- GEMM: Y[M,128] = X[M,128] @ W[128,128] (fp32) ------------
// Block: 64 rows x 128 cols. Threads 256 = 16(tr) x 16(tc).
// Thread tile: 4 rows x (4 + 4) cols (split halves for conflict-free LDS.128).
__global__ void __launch_bounds__(256) gemm128(const float* __restrict__ X,
                                               const float* __restrict__ W,
                                               int which, int M) {
    __shared__ float Ws[64][128];   // 32 KB  [k][j]
    __shared__ float Xs[64][64];    // 16 KB  [k][row] (transposed)

    float* __restrict__ Y = which ? g_xr : g_xl;

    const int tid  = threadIdx.x;
    const int tr   = tid >> 4;      // 0..15  -> rows tr*4 .. tr*4+3
    const int tc   = tid & 15;      // 0..15  -> cols tc*4.. and 64+tc*4..
    const int row0 = blockIdx.x * 64;

    float acc[4][8];
#pragma unroll
    for (int r = 0; r < 4; r++)
#pragma unroll
        for (int c = 0; c < 8; c++) acc[r][c] = 0.f;

    for (int k0 = 0; k0 < DD; k0 += 64) {
        // load W tile [64][128]: 2048 float4, 8 per thread, direct copy
#pragma unroll
        for (int i = tid; i < 64 * 32; i += 256) {
            int k = i >> 5, j4 = i & 31;
            ((float4*)Ws[k])[j4] = ((const float4*)(W + (size_t)(k0 + k) * DD))[j4];
        }
        // load X tile transposed: i -> (r = i&63, c4 = i>>6); STS conflict-free
#pragma unroll
        for (int i = tid; i < 1024; i += 256) {
            int r = i & 63, c4 = i >> 6;
            int row = row0 + r;
            float4 v = make_float4(0.f, 0.f, 0.f, 0.f);
            if (row < M) v = ((const float4*)(X + (size_t)row * DD + k0))[c4];
            Xs[c4 * 4 + 0][r] = v.x;
            Xs[c4 * 4 + 1][r] = v.y;
            Xs[c4 * 4 + 2][r] = v.z;
            Xs[c4 * 4 + 3][r] = v.w;
        }
        __syncthreads();

#pragma unroll 8
        for (int k = 0; k < 64; k++) {
            float4 xv = *(const float4*)&Xs[k][tr * 4];
            float4 w0 = *(const float4*)&Ws[k][tc * 4];        // cols tc*4..
            float4 w1 = *(const float4*)&Ws[k][64 + tc * 4];   // cols 64+tc*4..
            float xr_[4] = {xv.x, xv.y, xv.z, xv.w};
            float wv[8]  = {w0.x, w0.y, w0.z, w0.w, w1.x, w1.y, w1.z, w1.w};
#pragma unroll
            for (int r = 0; r < 4; r++)
#pragma unroll
                for (int c = 0; c < 8; c++)
                    acc[r][c] = fmaf(xr_[r], wv[c], acc[r][c]);
        }
        __syncthreads();
    }

#pragma unroll
    for (int r = 0; r < 4; r++) {
        int row = row0 + tr * 4 + r;
        if (row < M) {
            float4 o0 = make_float4(acc[r][0], acc[r][1], acc[r][2], acc[r][3]);
            float4 o1 = make_float4(acc[r][4], acc[r][5], acc[r][6], acc[r][7]);
            ((float4*)(Y + (size_t)row * DD))[tc]      = o0;  // cols tc*4..
            ((float4*)(Y + (size_t)row * DD))[16 + tc] = o1;  // cols 64+tc*4..
        }
    }
}

// ---------------- per-edge attention logits (warp per edge) ----------------
__device__ __forceinline__ float lrelu(float v) { return v > 0.f ? v : 0.2f * v; }

__global__ void edge_logits(const int* __restrict__ esrc, const int* __restrict__ edst,
                            const float* __restrict__ att) {
    int g = blockIdx.x * blockDim.x + threadIdx.x;
    int e = g >> 5, lane = g & 31;
    if (e >= NE) return;
    int s = esrc[e], d = edst[e];
    float4 a  = ((const float4*)att)[lane];
    float4 xj = ((const float4*)g_xl)[(size_t)s * 32 + lane];
    float4 xi = ((const float4*)g_xr)[(size_t)d * 32 + lane];
    float p = a.x * lrelu(xi.x + xj.x) + a.y * lrelu(xi.y + xj.y) +
              a.z * lrelu(xi.z + xj.z) + a.w * lrelu(xi.w + xj.w);
#pragma unroll
    for (int o = 16; o; o >>= 1) p += __shfl_xor_sync(0xffffffffu, p, o);
    if (!lane) g_e[e] = p;
}

// ---------------- CSR build ----------------
__global__ void zero_deg() {
    int i = blockIdx.x * blockDim.x + threadIdx.x;
    if (i < NN) g_deg[i] = 0;
}

__global__ void count_deg(const int* __restrict__ edst) {
    int i = blockIdx.x * blockDim.x + threadIdx.x;
    if (i < NE) atomicAdd(&g_deg[edst[i]], 1);
}

__global__ void scan_off() {   // single block, 1024 threads
    const int C = (NN + 1023) / 1024;   // 98
    int tid = threadIdx.x, base = tid * C;
    int s = 0;
    for (int i = 0; i < C; i++) {
        int j = base + i;
        if (j < NN) s += g_deg[j];
    }
    __shared__ int sh[1024];
    sh[tid] = s;
    __syncthreads();
    for (int o = 1; o < 1024; o <<= 1) {
        int v = (tid >= o) ? sh[tid - o] : 0;
        __syncthreads();
        sh[tid] += v;
        __syncthreads();
    }
    int run = sh[tid] - s;   // exclusive prefix
    for (int i = 0; i < C; i++) {
        int j = base + i;
        if (j < NN) {
            g_off[j] = run;
            g_cur[j] = run;
            run += g_deg[j];
        }
    }
    if (tid == 1023) g_off[NN] = run;   // == NE
}

__global__ void scatter_csr(const int* __restrict__ edst) {
    int i = blockIdx.x * blockDim.x + threadIdx.x;
    if (i < NE) {
        int p = atomicAdd(&g_cur[edst[i]], 1);
        g_eid[p] = i;
    }
}

// ---------------- per-dst softmax + mean aggregation (warp per node) -------
__global__ void node_agg(const int* __restrict__ esrc, const float* __restrict__ bias,
                         float* __restrict__ out) {
    int g = blockIdx.x * blockDim.x + threadIdx.x;
    int n = g >> 5, lane = g & 31;
    if (n >= NN) return;
    int start = g_off[n], end = g_off[n + 1];
    int deg = end - start;
    float4 b = ((const float4*)bias)[lane];
    if (deg == 0) {
        ((float4*)out)[(size_t)n * 32 + lane] = b;
        return;
    }
    // segment max
    float m = -3.402823466e38f;
    for (int k = start + lane; k < end; k += 32) m = fmaxf(m, g_e[g_eid[k]]);
#pragma unroll
    for (int o = 16; o; o >>= 1) m = fmaxf(m, __shfl_xor_sync(0xffffffffu, m, o));
    // segment sum of exp
    float s = 0.f;
    for (int k = start + lane; k < end; k += 32) s += __expf(g_e[g_eid[k]] - m);
#pragma unroll
    for (int o = 16; o; o >>= 1) s += __shfl_xor_sync(0xffffffffu, s, o);
    float inv = 1.f / fmaxf(s, 1e-16f);
    // weighted sum of gathered source features
    float4 acc = make_float4(0.f, 0.f, 0.f, 0.f);
    for (int k = start; k < end; k++) {
        int eid = g_eid[k];
        float a = __expf(g_e[eid] - m) * inv;
        int src = esrc[eid];
        float4 x = ((const float4*)g_xl)[(size_t)src * 32 + lane];
        acc.x = fmaf(a, x.x, acc.x);
        acc.y = fmaf(a, x.y, acc.y);
        acc.z = fmaf(a, x.z, acc.z);
        acc.w = fmaf(a, x.w, acc.w);
    }
    float invd = 1.f / (float)deg;
    float4 o_ = make_float4(fmaf(acc.x, invd, b.x), fmaf(acc.y, invd, b.y),
                            fmaf(acc.z, invd, b.z), fmaf(acc.w, invd, b.w));
    ((float4*)out)[(size_t)n * 32 + lane] = o_;
}

// ---------------- launch ----------------
extern "C" void kernel_launch(void* const* d_in, const int* in_sizes, int n_in,
                              void* d_out, int out_size) {
    const float* x_low  = (const float*)d_in[0];
    const float* x_high = (const float*)d_in[1];
    const float* W_l    = (const float*)d_in[2];
    const float* W_r    = (const float*)d_in[3];
    const float* att    = (const float*)d_in[4];
    const float* bias   = (const float*)d_in[5];
    const int*   esrc   = (const int*)d_in[6];
    const int*   edst   = (const int*)d_in[7];
    float*       out    = (float*)d_out;

    const int gemm_blocks = (NN + 63) / 64;          // 1563
    gemm128<<<gemm_blocks, 256>>>(x_low,  W_l, 0, NN);
    gemm128<<<gemm_blocks, 256>>>(x_high, W_r, 1, NN);

    // CSR chain is independent of the GEMMs; edge_logits depends on them.
    zero_deg<<<(NN + 511) / 512, 512>>>();
    count_deg<<<(NE + 511) / 512, 512>>>(edst);

    edge_logits<<<(NE * 32 + 255) / 256, 256>>>(esrc, edst, att);

    scan_off<<<1, 1024>>>();
    scatter_csr<<<(NE + 511) / 512, 512>>>(edst);

    node_agg<<<(NN * 32 + 255) / 256, 256>>>(esrc, bias, out);
}

// round 4
// speedup vs baseline: 1.0075x; 1.0075x over previous
#include <cuda_runtime.h>
#include <math.h>
#include <stdint.h>

#define NN 100000
#define NE 600000
#define DD 128

// ---------------- scratch (device globals: allocation-free) ----------------
__device__ float g_xl[NN * DD];   // x_low  @ W_l
__device__ float g_xr[NN * DD];   // x_high @ W_r
__device__ float g_e[NE];         // per-edge attention logits
__device__ int   g_deg[NN];
__device__ int   g_off[NN + 1];
__device__ int   g_cur[NN];
__device__ int   g_eid[NE];       // CSR (by dst) edge ids

// ---------------- tf32 helpers ----------------
__device__ __forceinline__ uint32_t f2tf32(float f) {
    uint32_t r;
    asm("cvt.rna.tf32.f32 %0, %1;" : "=r"(r) : "f"(f));
    return r;
}

__device__ __forceinline__ void mma_tf32(float c[4], const uint32_t a[4], const uint32_t b[2]) {
    asm volatile(
        "mma.sync.aligned.m16n8k8.row.col.f32.tf32.tf32.f32 "
        "{%0,%1,%2,%3}, {%4,%5,%6,%7}, {%8,%9}, {%0,%1,%2,%3};\n"
        : "+f"(c[0]), "+f"(c[1]), "+f"(c[2]), "+f"(c[3])
        : "r"(a[0]), "r"(a[1]), "r"(a[2]), "r"(a[3]), "r"(b[0]), "r"(b[1]));
}

// ---------------- GEMM: Y[M,128] = X[M,128] @ W[128,128]  (tf32 tensor core)
// Block: 128-row output tile, full K=128. 256 threads = 8 warps (2 M x 4 N).
// Warp tile 64x32 = 4x4 mma(m16n8k8) tiles, 16 K-steps.
// Smem: Xs[128][132] (A, row-major, pad->conflict-free), Ws[128][136] (B, k-major).
#define XS_STRIDE 132
#define WS_STRIDE 136
#define GEMM_SMEM ((128 * XS_STRIDE + 128 * WS_STRIDE) * 4)

__global__ void __launch_bounds__(256) gemm_tf32(const float* __restrict__ X0,
                                                 const float* __restrict__ X1,
                                                 const float* __restrict__ W0,
                                                 const float* __restrict__ W1) {
    extern __shared__ uint32_t sh[];
    uint32_t* Xs = sh;                       // [128][XS_STRIDE]
    uint32_t* Ws = sh + 128 * XS_STRIDE;     // [128][WS_STRIDE]

    const int which = blockIdx.y;
    const float* __restrict__ X = which ? X1 : X0;
    const float* __restrict__ W = which ? W1 : W0;
    float* __restrict__ Y = which ? g_xr : g_xl;

    const int tid  = threadIdx.x;
    const int row0 = blockIdx.x * 128;

    // Load W[128][128] -> Ws (tf32), float4 global loads, uint4 smem stores.
    for (int i = tid; i < 128 * 32; i += 256) {
        int k = i >> 5, c4 = i & 31;
        float4 v = ((const float4*)(W + (size_t)k * DD))[c4];
        uint4 t = make_uint4(f2tf32(v.x), f2tf32(v.y), f2tf32(v.z), f2tf32(v.w));
        *(uint4*)&Ws[k * WS_STRIDE + c4 * 4] = t;
    }
    // Load X tile [128][128] -> Xs (tf32), zero-pad past M.
    for (int i = tid; i < 128 * 32; i += 256) {
        int r = i >> 5, c4 = i & 31;
        int row = row0 + r;
        float4 v = make_float4(0.f, 0.f, 0.f, 0.f);
        if (row < NN) v = ((const float4*)(X + (size_t)row * DD))[c4];
        uint4 t = make_uint4(f2tf32(v.x), f2tf32(v.y), f2tf32(v.z), f2tf32(v.w));
        *(uint4*)&Xs[r * XS_STRIDE + c4 * 4] = t;
    }
    __syncthreads();

    const int wid  = tid >> 5, lane = tid & 31;
    const int gID  = lane >> 2, tig = lane & 3;
    const int wm   = (wid >> 2) * 64;    // warp M base (0 or 64)
    const int wn   = (wid & 3) * 32;     // warp N base (0,32,64,96)

    float acc[4][4][4];
#pragma unroll
    for (int i = 0; i < 4; i++)
#pragma unroll
        for (int j = 0; j < 4; j++)
#pragma unroll
            for (int q = 0; q < 4; q++) acc[i][j][q] = 0.f;

#pragma unroll
    for (int k0 = 0; k0 < 128; k0 += 8) {
        uint32_t a[4][4], b[4][2];
#pragma unroll
        for (int i = 0; i < 4; i++) {
            int r = wm + i * 16 + gID;
            a[i][0] = Xs[r * XS_STRIDE + k0 + tig];
            a[i][1] = Xs[(r + 8) * XS_STRIDE + k0 + tig];
            a[i][2] = Xs[r * XS_STRIDE + k0 + tig + 4];
            a[i][3] = Xs[(r + 8) * XS_STRIDE + k0 + tig + 4];
        }
#pragma unroll
        for (int j = 0; j < 4; j++) {
            int c = wn + j * 8 + gID;
            b[j][0] = Ws[(k0 + tig) * WS_STRIDE + c];
            b[j][1] = Ws[(k0 + tig + 4) * WS_STRIDE + c];
        }
#pragma unroll
        for (int i = 0; i < 4; i++)
#pragma unroll
            for (int j = 0; j < 4; j++) mma_tf32(acc[i][j], a[i], b[j]);
    }

    // Store: thread owns rows (gID, gID+8) of each 16-row tile, cols 2*tig..
#pragma unroll
    for (int i = 0; i < 4; i++) {
        int row_a = row0 + wm + i * 16 + gID;
        int row_b = row_a + 8;
#pragma unroll
        for (int j = 0; j < 4; j++) {
            int col = wn + j * 8 + tig * 2;
            if (row_a < NN)
                *(float2*)(Y + (size_t)row_a * DD + col) = make_float2(acc[i][j][0], acc[i][j][1]);
            if (row_b < NN)
                *(float2*)(Y + (size_t)row_b * DD + col) = make_float2(acc[i][j][2], acc[i][j][3]);
        }
    }
}

// ---------------- per-edge attention logits (warp per edge) ----------------
__device__ __forceinline__ float lrelu(float v) { return v > 0.f ? v : 0.2f * v; }

__global__ void edge_logits(const int* __restrict__ esrc, const int* __restrict__ edst,
                            const float* __restrict__ att) {
    int g = blockIdx.x * blockDim.x + threadIdx.x;
    int e = g >> 5, lane = g & 31;
    if (e >= NE) return;
    int s = esrc[e], d = edst[e];
    float4 a  = ((const float4*)att)[lane];
    float4 xj = ((const float4*)g_xl)[(size_t)s * 32 + lane];
    float4 xi = ((const float4*)g_xr)[(size_t)d * 32 + lane];
    float p = a.x * lrelu(xi.x + xj.x) + a.y * lrelu(xi.y + xj.y) +
              a.z * lrelu(xi.z + xj.z) + a.w * lrelu(xi.w + xj.w);
#pragma unroll
    for (int o = 16; o; o >>= 1) p += __shfl_xor_sync(0xffffffffu, p, o);
    if (!lane) g_e[e] = p;
}

// ---------------- CSR build ----------------
__global__ void zero_deg() {
    int i = blockIdx.x * blockDim.x + threadIdx.x;
    if (i < NN) g_deg[i] = 0;
}

__global__ void count_deg(const int* __restrict__ edst) {
    int i = blockIdx.x * blockDim.x + threadIdx.x;
    if (i < NE) atomicAdd(&g_deg[edst[i]], 1);
}

__global__ void scan_off() {   // single block, 1024 threads
    const int C = (NN + 1023) / 1024;   // 98
    int tid = threadIdx.x, base = tid * C;
    int s = 0;
    for (int i = 0; i < C; i++) {
        int j = base + i;
        if (j < NN) s += g_deg[j];
    }
    __shared__ int sh[1024];
    sh[tid] = s;
    __syncthreads();
    for (int o = 1; o < 1024; o <<= 1) {
        int v = (tid >= o) ? sh[tid - o] : 0;
        __syncthreads();
        sh[tid] += v;
        __syncthreads();
    }
    int run = sh[tid] - s;   // exclusive prefix
    for (int i = 0; i < C; i++) {
        int j = base + i;
        if (j < NN) {
            g_off[j] = run;
            g_cur[j] = run;
            run += g_deg[j];
        }
    }
    if (tid == 1023) g_off[NN] = run;   // == NE
}

__global__ void scatter_csr(const int* __restrict__ edst) {
    int i = blockIdx.x * blockDim.x + threadIdx.x;
    if (i < NE) {
        int p = atomicAdd(&g_cur[edst[i]], 1);
        g_eid[p] = i;
    }
}

// ---------------- per-dst softmax + mean aggregation (warp per node) -------
__global__ void node_agg(const int* __restrict__ esrc, const float* __restrict__ bias,
                         float* __restrict__ out) {
    int g = blockIdx.x * blockDim.x + threadIdx.x;
    int n = g >> 5, lane = g & 31;
    if (n >= NN) return;
    int start = g_off[n], end = g_off[n + 1];
    int deg = end - start;
    float4 b = ((const float4*)bias)[lane];
    if (deg == 0) {
        ((float4*)out)[(size_t)n * 32 + lane] = b;
        return;
    }
    // segment max
    float m = -3.402823466e38f;
    for (int k = start + lane; k < end; k += 32) m = fmaxf(m, g_e[g_eid[k]]);
#pragma unroll
    for (int o = 16; o; o >>= 1) m = fmaxf(m, __shfl_xor_sync(0xffffffffu, m, o));
    // segment sum of exp
    float s = 0.f;
    for (int k = start + lane; k < end; k += 32) s += __expf(g_e[g_eid[k]] - m);
#pragma unroll
    for (int o = 16; o; o >>= 1) s += __shfl_xor_sync(0xffffffffu, s, o);
    float inv = 1.f / fmaxf(s, 1e-16f);
    // weighted sum of gathered source features
    float4 acc = make_float4(0.f, 0.f, 0.f, 0.f);
    for (int k = start; k < end; k++) {
        int eid = g_eid[k];
        float a = __expf(g_e[eid] - m) * inv;
        int src = esrc[eid];
        float4 x = ((const float4*)g_xl)[(size_t)src * 32 + lane];
        acc.x = fmaf(a, x.x, acc.x);
        acc.y = fmaf(a, x.y, acc.y);
        acc.z = fmaf(a, x.z, acc.z);
        acc.w = fmaf(a, x.w, acc.w);
    }
    float invd = 1.f / (float)deg;
    float4 o_ = make_float4(fmaf(acc.x, invd, b.x), fmaf(acc.y, invd, b.y),
                            fmaf(acc.z, invd, b.z), fmaf(acc.w, invd, b.w));
    ((float4*)out)[(size_t)n * 32 + lane] = o_;
}

// ---------------- launch ----------------
extern "C" void kernel_launch(void* const* d_in, const int* in_sizes, int n_in,
                              void* d_out, int out_size) {
    const float* x_low  = (const float*)d_in[0];
    const float* x_high = (const float*)d_in[1];
    const float* W_l    = (const float*)d_in[2];
    const float* W_r    = (const float*)d_in[3];
    const float* att    = (const float*)d_in[4];
    const float* bias   = (const float*)d_in[5];
    const int*   esrc   = (const int*)d_in[6];
    const int*   edst   = (const int*)d_in[7];
    float*       out    = (float*)d_out;

    cudaFuncSetAttribute(gemm_tf32, cudaFuncAttributeMaxDynamicSharedMemorySize, GEMM_SMEM);

    dim3 ggrid((NN + 127) / 128, 2);   // 782 x 2
    gemm_tf32<<<ggrid, 256, GEMM_SMEM>>>(x_low, x_high, W_l, W_r);

    // CSR chain is independent of the GEMMs; edge_logits depends on them.
    zero_deg<<<(NN + 511) / 512, 512>>>();
    count_deg<<<(NE + 511) / 512, 512>>>(edst);

    edge_logits<<<(NE * 32 + 255) / 256, 256>>>(esrc, edst, att);

    scan_off<<<1, 1024>>>();
    scatter_csr<<<(NE + 511) / 512, 512>>>(edst);

    node_agg<<<(NN * 32 + 255) / 256, 256>>>(esrc, bias, out);
}